// round 4
// baseline (speedup 1.0000x reference)
#include <cuda_runtime.h>
#include <cuda_bf16.h>
#include <stdint.h>
#include <math.h>

#define Dc 256
#define Kc 64
#define TN 64
#define NTHREADS 256

#if defined(__CUDA_ARCH_FEAT_SM103_ALL) || defined(__CUDA_ARCH_FEAT_SM100_ALL)
#define TC_OK 1
#else
#define TC_OK 0
#endif

// ---- shared memory layout (bytes, from dynamic smem base) ----
#define SM_TMEMPTR 0
#define SM_MB1     16
#define SM_MB2     24
#define SM_B       32          // 64 floats bias
#define SM_WH      1024        // W hi  [64k][256d] bf16 blocked-atom SW128  (32KB)
#define SM_WL      (SM_WH  + 32768)
#define SM_XTH     (SM_WL  + 32768)   // X^T hi [64n][256d]
#define SM_XTL     (SM_XTH + 32768)
#define SM_XDH     (SM_XTL + 32768)   // X hi [256d][64n]
#define SM_XDL     (SM_XDH + 32768)
#define SM_AH      (SM_XDL + 32768)   // a hi [64k][64n]  (8KB)
#define SM_AL      (SM_AH  + 8192)
#define SM_TOTAL   (SM_AL  + 8192)    // 214016 B

// idesc: kind::f16, dtype=F32, atype=btype=BF16, N=64, M=128
#define IDESC ((1u<<4) | (1u<<7) | (1u<<10) | (8u<<17) | (8u<<24))

#define SWZ(o) ((o) ^ (((o) >> 3) & 0x70))

// SW128 K-major descriptor base: layout=2, version=1, SBO=64, LBO=1
#define DESC_BASE 0x4000404000010000ULL

__device__ float g_V[Kc * Dc];
__device__ float g_asum[Kc];

// ------------------------- PTX helpers -------------------------
__device__ __forceinline__ uint32_t smem_u32(const void* p) {
    uint32_t a;
    asm("{ .reg .u64 t; cvta.to.shared.u64 t, %1; cvt.u32.u64 %0, t; }" : "=r"(a) : "l"(p));
    return a;
}
__device__ __forceinline__ uint64_t make_desc(uint32_t addr) {
    return DESC_BASE | ((uint64_t)(addr >> 4) & 0x3FFF);
}
#if TC_OK
__device__ __forceinline__ void mma_f16_ss(uint32_t d_tmem, uint64_t a_desc,
                                           uint64_t b_desc, uint32_t idesc, int acc) {
    asm volatile(
        "{\n\t.reg .pred p;\n\tsetp.ne.u32 p, %4, 0;\n\t"
        "tcgen05.mma.cta_group::1.kind::f16 [%0], %1, %2, %3, {%5, %5, %5, %5}, p;\n\t}"
        :: "r"(d_tmem), "l"(a_desc), "l"(b_desc), "r"(idesc), "r"((uint32_t)acc), "r"(0u)
        : "memory");
}
#endif
#define TC_COMMIT(mbar) \
    asm volatile("tcgen05.commit.cta_group::1.mbarrier::arrive::one.shared::cluster.b64 [%0];" \
                 :: "r"(mbar) : "memory")
#define TC_ALLOC(dst, n) \
    asm volatile("tcgen05.alloc.cta_group::1.sync.aligned.shared::cta.b32 [%0], %1;" \
                 :: "r"(dst), "r"(n) : "memory")
#define TC_RELINQ() asm volatile("tcgen05.relinquish_alloc_permit.cta_group::1.sync.aligned;")
#define TC_DEALLOC(base, n) \
    asm volatile("tcgen05.dealloc.cta_group::1.sync.aligned.b32 %0, %1;" :: "r"(base), "r"(n))
#define TC_WAIT_LD() asm volatile("tcgen05.wait::ld.sync.aligned;" ::: "memory")
#define TC_FENCE_AFTER() asm volatile("tcgen05.fence::after_thread_sync;" ::: "memory")
#define FENCE_ASYNC() asm volatile("fence.proxy.async.shared::cta;" ::: "memory")
#define MB_INIT(addr, cnt) \
    asm volatile("mbarrier.init.shared.b64 [%0], %1;" :: "r"(addr), "r"((uint32_t)(cnt)) : "memory")
#define MB_INVAL(addr) asm volatile("mbarrier.inval.shared.b64 [%0];" :: "r"(addr) : "memory")

#define MB_WAIT(mbar, ph) do {                                                  \
    uint32_t _m = (mbar); uint32_t _p = (uint32_t)(ph); uint32_t _done;         \
    asm volatile("{\n\t.reg .pred p;\n\t"                                       \
        "mbarrier.try_wait.parity.acquire.cta.shared::cta.b64 p, [%1], %2;\n\t" \
        "selp.b32 %0, 1, 0, p;\n\t}" : "=r"(_done) : "r"(_m), "r"(_p) : "memory"); \
    if (!_done) {                                                               \
        asm volatile("{\n\t.reg .pred P1;\n\t"                                  \
            "WL_%=:\n\t"                                                        \
            "mbarrier.try_wait.parity.acquire.cta.shared::cta.b64 P1, [%0], %1, 0x989680;\n\t" \
            "@P1 bra.uni WD_%=;\n\t"                                            \
            "bra.uni WL_%=;\n\t"                                                \
            "WD_%=:\n\t}" :: "r"(_m), "r"(_p) : "memory");                      \
    }                                                                           \
} while (0)

#define TC_LD_X32(r, addr)                                                      \
    asm volatile("tcgen05.ld.sync.aligned.32x32b.x32.b32 "                      \
        "{%0, %1, %2, %3, %4, %5, %6, %7, %8, %9, %10, %11, %12, %13, %14, %15, " \
        " %16, %17, %18, %19, %20, %21, %22, %23, %24, %25, %26, %27, %28, %29, %30, %31}, [%32];" \
        : "=r"((r)[0]),  "=r"((r)[1]),  "=r"((r)[2]),  "=r"((r)[3]),            \
          "=r"((r)[4]),  "=r"((r)[5]),  "=r"((r)[6]),  "=r"((r)[7]),            \
          "=r"((r)[8]),  "=r"((r)[9]),  "=r"((r)[10]), "=r"((r)[11]),           \
          "=r"((r)[12]), "=r"((r)[13]), "=r"((r)[14]), "=r"((r)[15]),           \
          "=r"((r)[16]), "=r"((r)[17]), "=r"((r)[18]), "=r"((r)[19]),           \
          "=r"((r)[20]), "=r"((r)[21]), "=r"((r)[22]), "=r"((r)[23]),           \
          "=r"((r)[24]), "=r"((r)[25]), "=r"((r)[26]), "=r"((r)[27]),           \
          "=r"((r)[28]), "=r"((r)[29]), "=r"((r)[30]), "=r"((r)[31])            \
        : "r"(addr))

__device__ __forceinline__ uint32_t pack2(__nv_bfloat16 a, __nv_bfloat16 b) {
    return (uint32_t)__bfloat16_as_ushort(a) | ((uint32_t)__bfloat16_as_ushort(b) << 16);
}
__device__ __forceinline__ void split2(float v, __nv_bfloat16& h, __nv_bfloat16& l) {
    h = __float2bfloat16_rn(v);
    l = __float2bfloat16_rn(v - __bfloat162float(h));
}

// ------------------------- kernels -------------------------
__global__ void zero_kernel() {
    int t = blockIdx.x * blockDim.x + threadIdx.x;
    if (t < Kc * Dc) g_V[t] = 0.0f;
    if (t < Kc) g_asum[t] = 0.0f;
}

__global__ __launch_bounds__(NTHREADS, 1) __cluster_dims__(1, 1, 1)
void netvlad_tc_kernel(const float* __restrict__ x,
                       const float* __restrict__ conv_w,
                       const float* __restrict__ conv_b,
                       int N, int numTiles) {
#if TC_OK
    extern __shared__ char smem[];
    const uint32_t sbase = smem_u32(smem);
    const int tid = threadIdx.x;
    const int wid = tid >> 5;

    // init
    if (tid == 0) { MB_INIT(sbase + SM_MB1, 1); MB_INIT(sbase + SM_MB2, 1); }
    if (wid == 0) { TC_ALLOC(sbase + SM_TMEMPTR, 256); TC_RELINQ(); }
    if (tid < Kc) *(float*)(smem + SM_B + tid * 4) = conv_b[tid];
    __syncthreads();
    uint32_t tmem;
    asm volatile("ld.shared.b32 %0, [%1];" : "=r"(tmem) : "r"(sbase + SM_TMEMPTR));

    // stage W hi/lo (blocked-atom SW128, K-major rows=k, cols=d, atom_rows=8)
    for (int i = tid; i < (Kc * Dc) / 4; i += NTHREADS) {
        int k = i >> 6;
        int d0 = (i & 63) * 4;
        float4 w4 = reinterpret_cast<const float4*>(conv_w)[i];
        __nv_bfloat16 h0, h1, h2, h3, l0, l1, l2, l3;
        split2(w4.x, h0, l0); split2(w4.y, h1, l1); split2(w4.z, h2, l2); split2(w4.w, h3, l3);
        uint32_t o = ((uint32_t)((k >> 3) + ((d0 >> 6) << 3)) << 10) + ((k & 7) << 7) + ((d0 & 63) << 1);
        o = SWZ(o);
        *(uint2*)(smem + SM_WH + o) = make_uint2(pack2(h0, h1), pack2(h2, h3));
        *(uint2*)(smem + SM_WL + o) = make_uint2(pack2(l0, l1), pack2(l2, l3));
    }

    // descriptors
    const uint64_t dWh  = make_desc(sbase + SM_WH);
    const uint64_t dWl  = make_desc(sbase + SM_WL);
    const uint64_t dXtH = make_desc(sbase + SM_XTH);
    const uint64_t dXtL = make_desc(sbase + SM_XTL);
    const uint64_t dXdH = make_desc(sbase + SM_XDH);
    const uint64_t dXdL = make_desc(sbase + SM_XDL);
    const uint64_t dAH  = make_desc(sbase + SM_AH);
    const uint64_t dAL  = make_desc(sbase + SM_AL);
    const float* sBf = (const float*)(smem + SM_B);

    float asum_local = 0.0f;
    int ph1 = 0, ph2 = 0, cnt = 0;

    for (int tile = blockIdx.x; tile < numTiles; tile += gridDim.x, cnt++) {
        const int n0 = tile * TN;

        // ---- 1) stage loads from gmem into registers ----
        float4 v[16];
#pragma unroll
        for (int j = 0; j < 16; j++) {
            int i = tid + NTHREADS * j;
            int d = i >> 4, n4 = i & 15;
            v[j] = *(reinterpret_cast<const float4*>(x + (size_t)d * N + n0) + n4);
        }

        // ---- 2) wait prev GEMM2 (protects Xd/a/Xt), sync (protects sA readers) ----
        if (cnt > 0) { MB_WAIT(sbase + SM_MB2, ph2); ph2 ^= 1; }
        __syncthreads();

        // ---- 3) convert + store X tiles (both layouts, hi/lo) ----
#pragma unroll
        for (int j = 0; j < 16; j++) {
            int i = tid + NTHREADS * j;
            int d = i >> 4;
            int n = (i & 15) * 4;
            float4 vv = v[j];
            __nv_bfloat16 h0, h1, h2, h3, l0, l1, l2, l3;
            split2(vv.x, h0, l0); split2(vv.y, h1, l1); split2(vv.z, h2, l2); split2(vv.w, h3, l3);
            // Xd [d][n], atoms of 8 d-rows x 128B
            uint32_t od = ((uint32_t)(d >> 3) << 10) + ((d & 7) << 7) + (n << 1);
            od = SWZ(od);
            *(uint2*)(smem + SM_XDH + od) = make_uint2(pack2(h0, h1), pack2(h2, h3));
            *(uint2*)(smem + SM_XDL + od) = make_uint2(pack2(l0, l1), pack2(l2, l3));
            // Xt [n][d], R=64 atom_rows=8, C=256 -> 4 atom-cols
            __nv_bfloat16 hh[4] = {h0, h1, h2, h3};
            __nv_bfloat16 ll[4] = {l0, l1, l2, l3};
#pragma unroll
            for (int t = 0; t < 4; t++) {
                int nn = n + t;
                uint32_t ot = ((uint32_t)((nn >> 3) + ((d >> 6) << 3)) << 10) + ((nn & 7) << 7) + ((d & 63) << 1);
                ot = SWZ(ot);
                *(__nv_bfloat16*)(smem + SM_XTH + ot) = hh[t];
                *(__nv_bfloat16*)(smem + SM_XTL + ot) = ll[t];
            }
        }
        FENCE_ASYNC();
        __syncthreads();

        // ---- 4) GEMM1: D1[pix][k] = Xh*Wh + Xh*Wl + Xl*Wh ----
        if (tid == 0) {
#pragma unroll
            for (int t = 0; t < 3; t++) {
                uint64_t at = (t == 2) ? dXtL : dXtH;
                uint64_t bt = (t == 1) ? dWl : dWh;
#pragma unroll
                for (int s = 0; s < 16; s++) {
                    uint64_t off = (uint64_t)(((s >> 2) * 512) + ((s & 3) * 2));
                    mma_f16_ss(tmem, at + off, bt + off, IDESC, (t | s) != 0);
                }
            }
            TC_COMMIT(sbase + SM_MB1);
        }
        MB_WAIT(sbase + SM_MB1, ph1); ph1 ^= 1;
        TC_FENCE_AFTER();

        // ---- 5) softmax per pixel (lane = pixel), store a hi/lo ----
        if (tid < TN) {
            uint32_t au[64];
            TC_LD_X32(au, tmem);
            TC_LD_X32(au + 32, tmem + 32);
            TC_WAIT_LD();
            float m = -1e30f;
#pragma unroll
            for (int c = 0; c < 64; c++) {
                float t = __uint_as_float(au[c]) + sBf[c];
                au[c] = __float_as_uint(t);
                m = fmaxf(m, t);
            }
            float s = 0.0f;
#pragma unroll
            for (int c = 0; c < 64; c++) {
                float e = __expf(__uint_as_float(au[c]) - m);
                au[c] = __float_as_uint(e);
                s += e;
            }
            float rinv = 1.0f / s;
#pragma unroll
            for (int c = 0; c < 64; c++) {
                float aa = __uint_as_float(au[c]) * rinv;
                __nv_bfloat16 h, l;
                split2(aa, h, l);
                uint32_t o = ((uint32_t)(c >> 3) << 10) + ((c & 7) << 7) + (tid << 1);
                o = SWZ(o);
                *(__nv_bfloat16*)(smem + SM_AH + o) = h;
                *(__nv_bfloat16*)(smem + SM_AL + o) = l;
            }
        }
        FENCE_ASYNC();
        __syncthreads();

        // ---- 6) GEMM2: D2[d][k] += Xd*a^T (3 split terms, 2 d-halves) ----
        if (tid == 0) {
#pragma unroll
            for (int h = 0; h < 2; h++) {
#pragma unroll
                for (int t = 0; t < 3; t++) {
                    uint64_t at = ((t == 1) ? dXdL : dXdH) + (uint64_t)(h * 1024);
                    uint64_t bt = (t == 2) ? dAL : dAH;
#pragma unroll
                    for (int s = 0; s < 4; s++) {
                        int acc = !(cnt == 0 && t == 0 && s == 0);
                        mma_f16_ss(tmem + 64 + 64 * h, at + (uint64_t)(s * 2), bt + (uint64_t)(s * 2), IDESC, acc);
                    }
                }
            }
            TC_COMMIT(sbase + SM_MB2);
        }

        // ---- 7) asum[k] partial: sum row k of stored a (hi+lo); overlaps MMA ----
        if (tid < Kc) {
            uint32_t rb = ((uint32_t)(tid >> 3) << 10) + ((tid & 7) << 7);
            float s = 0.0f;
#pragma unroll
            for (int j = 0; j < 8; j++) {
                uint4 uh = *(const uint4*)(smem + SM_AH + rb + 16 * j);
                uint4 ul = *(const uint4*)(smem + SM_AL + rb + 16 * j);
                float2 f;
                f = __bfloat1622float2(*(__nv_bfloat162*)&uh.x); s += f.x + f.y;
                f = __bfloat1622float2(*(__nv_bfloat162*)&uh.y); s += f.x + f.y;
                f = __bfloat1622float2(*(__nv_bfloat162*)&uh.z); s += f.x + f.y;
                f = __bfloat1622float2(*(__nv_bfloat162*)&uh.w); s += f.x + f.y;
                f = __bfloat1622float2(*(__nv_bfloat162*)&ul.x); s += f.x + f.y;
                f = __bfloat1622float2(*(__nv_bfloat162*)&ul.y); s += f.x + f.y;
                f = __bfloat1622float2(*(__nv_bfloat162*)&ul.z); s += f.x + f.y;
                f = __bfloat1622float2(*(__nv_bfloat162*)&ul.w); s += f.x + f.y;
            }
            asum_local += s;
        }
    }

    // ---- final flush ----
    if (cnt > 0) {
        MB_WAIT(sbase + SM_MB2, ph2); ph2 ^= 1;
        TC_FENCE_AFTER();
        uint32_t r[64];
        uint32_t cbase = tmem + 64 + ((tid >= 128) ? 64 : 0);
        TC_LD_X32(r, cbase);
        TC_LD_X32(r + 32, cbase + 32);
        TC_WAIT_LD();
#pragma unroll
        for (int c = 0; c < 64; c++)
            atomicAdd(&g_V[c * Dc + tid], __uint_as_float(r[c]));
        if (tid < Kc) atomicAdd(&g_asum[tid], asum_local);
    }
    __syncthreads();
    if (tid == 0) { MB_INVAL(sbase + SM_MB1); MB_INVAL(sbase + SM_MB2); }
    __syncthreads();
    if (wid == 0) TC_DEALLOC(tmem, 256);
#else
    // ---------- FFMA fallback (correct on non-a targets; never the fast path) ----------
    extern __shared__ float fsm[];
    float* sW  = fsm;                  // [64][257]
    float* sXT = sW + Kc * 257;        // [64][257]
    float* sA  = sXT + TN * 257;       // [64][65]
    float* sB  = sA + Kc * 65;         // [64]
    const int tid = threadIdx.x;
    for (int i = tid; i < (Kc * Dc) / 4; i += NTHREADS) {
        int k = (i * 4) / Dc, d = (i * 4) % Dc;
        float4 w4 = reinterpret_cast<const float4*>(conv_w)[i];
        float* p = &sW[k * 257 + d];
        p[0] = w4.x; p[1] = w4.y; p[2] = w4.z; p[3] = w4.w;
    }
    if (tid < Kc) sB[tid] = conv_b[tid];
    const int tn = tid & 15, tk = tid >> 4;
    const int td = tid & 31, tk2 = tid >> 5;
    float vacc[8][8];
#pragma unroll
    for (int i = 0; i < 8; i++)
#pragma unroll
        for (int j = 0; j < 8; j++) vacc[i][j] = 0.0f;
    float asum_acc = 0.0f;
    for (int tile = blockIdx.x; tile < numTiles; tile += gridDim.x) {
        const int n0 = tile * TN;
        __syncthreads();
        for (int i = tid; i < (Dc * TN) / 4; i += NTHREADS) {
            int d = i >> 4, ng = i & 15;
            float4 v = reinterpret_cast<const float4*>(x + (size_t)d * N + n0)[ng];
            int nb = ng * 4;
            sXT[(nb + 0) * 257 + d] = v.x; sXT[(nb + 1) * 257 + d] = v.y;
            sXT[(nb + 2) * 257 + d] = v.z; sXT[(nb + 3) * 257 + d] = v.w;
        }
        __syncthreads();
        float acc[4][4];
#pragma unroll
        for (int i = 0; i < 4; i++)
#pragma unroll
            for (int j = 0; j < 4; j++) acc[i][j] = 0.0f;
#pragma unroll 4
        for (int d = 0; d < Dc; d++) {
            float wv[4], xv[4];
#pragma unroll
            for (int i = 0; i < 4; i++) wv[i] = sW[(tk * 4 + i) * 257 + d];
#pragma unroll
            for (int j = 0; j < 4; j++) xv[j] = sXT[(tn * 4 + j) * 257 + d];
#pragma unroll
            for (int i = 0; i < 4; i++)
#pragma unroll
                for (int j = 0; j < 4; j++) acc[i][j] += wv[i] * xv[j];
        }
#pragma unroll
        for (int i = 0; i < 4; i++) {
            float b = sB[tk * 4 + i];
#pragma unroll
            for (int j = 0; j < 4; j++)
                sA[(tk * 4 + i) * 65 + (tn * 4 + j)] = acc[i][j] + b;
        }
        __syncthreads();
        if (tid < TN) {
            const int n = tid;
            float m = -1e30f;
            for (int k = 0; k < Kc; k++) m = fmaxf(m, sA[k * 65 + n]);
            float s = 0.0f;
            for (int k = 0; k < Kc; k++) {
                float e = __expf(sA[k * 65 + n] - m);
                sA[k * 65 + n] = e; s += e;
            }
            float r = 1.0f / s;
            for (int k = 0; k < Kc; k++) sA[k * 65 + n] *= r;
        }
        __syncthreads();
        if (tid < Kc) {
            float s = 0.0f;
            for (int n = 0; n < TN; n++) s += sA[tid * 65 + n];
            asum_acc += s;
        }
#pragma unroll 2
        for (int n = 0; n < TN; n++) {
            float av[8], xv[8];
#pragma unroll
            for (int i = 0; i < 8; i++) av[i] = sA[(tk2 * 8 + i) * 65 + n];
#pragma unroll
            for (int j = 0; j < 8; j++) xv[j] = sXT[n * 257 + td + 32 * j];
#pragma unroll
            for (int i = 0; i < 8; i++)
#pragma unroll
                for (int j = 0; j < 8; j++) vacc[i][j] += av[i] * xv[j];
        }
    }
#pragma unroll
    for (int i = 0; i < 8; i++)
#pragma unroll
        for (int j = 0; j < 8; j++)
            atomicAdd(&g_V[(tk2 * 8 + i) * Dc + td + 32 * j], vacc[i][j]);
    if (tid < Kc) atomicAdd(&g_asum[tid], asum_acc);
#endif
}

#define SW_STRIDE 257
__global__ void finalize_kernel(const float* __restrict__ c,
                                float* __restrict__ out) {
    extern __shared__ float fsm2[];
    float* sV = fsm2;                     // [64][257]
    float* sAs = sV + Kc * SW_STRIDE;     // [64]
    const int tid = threadIdx.x;          // 256 threads
    if (tid < Kc) sAs[tid] = g_asum[tid];
    __syncthreads();
    const int d = tid;
    float ss = 0.0f;
    for (int k = 0; k < Kc; k++) {
        float v = g_V[k * Dc + d] - c[k * Dc + d] * sAs[k];
        sV[k * SW_STRIDE + d] = v;
        ss += v * v;
    }
    float r = 1.0f / fmaxf(sqrtf(ss), 1e-12f);
    for (int k = 0; k < Kc; k++) sV[k * SW_STRIDE + d] *= r;
    __syncthreads();
    if (tid < Kc) {
        const int k = tid;
        float rs = 0.0f;
        for (int dd = 0; dd < Dc; dd++) {
            float v = sV[k * SW_STRIDE + dd];
            rs += v * v;
        }
        float rr = 1.0f / fmaxf(sqrtf(rs), 1e-12f);
        for (int dd = 0; dd < Dc; dd++)
            out[k * Dc + dd] = sV[k * SW_STRIDE + dd] * rr;
    }
}

extern "C" void kernel_launch(void* const* d_in, const int* in_sizes, int n_in,
                              void* d_out, int out_size) {
    const float* x      = (const float*)d_in[0];
    const float* c      = (const float*)d_in[1];
    const float* conv_w = (const float*)d_in[2];
    const float* conv_b = (const float*)d_in[3];
    float* out = (float*)d_out;

    const int N = in_sizes[0] / Dc;
    const int numTiles = N / TN;

    int nsm = 148;
    cudaDeviceGetAttribute(&nsm, cudaDevAttrMultiProcessorCount, 0);

    cudaFuncSetAttribute(netvlad_tc_kernel,
                         cudaFuncAttributeMaxDynamicSharedMemorySize, SM_TOTAL);
    const int fin_smem = (Kc * SW_STRIDE + Kc) * (int)sizeof(float);
    cudaFuncSetAttribute(finalize_kernel,
                         cudaFuncAttributeMaxDynamicSharedMemorySize, fin_smem);

    zero_kernel<<<(Kc * Dc + 255) / 256, 256>>>();
    netvlad_tc_kernel<<<nsm, NTHREADS, SM_TOTAL>>>(x, conv_w, conv_b, N, numTiles);
    finalize_kernel<<<1, 256, fin_smem>>>(c, out);
}

// round 5
// speedup vs baseline: 1.3687x; 1.3687x over previous
#include <cuda_runtime.h>
#include <cuda_bf16.h>
#include <stdint.h>
#include <math.h>

#define Dc 256
#define Kc 64
#define TN 64
#define NTHREADS 256

#if defined(__CUDA_ARCH_FEAT_SM103_ALL) || defined(__CUDA_ARCH_FEAT_SM100_ALL)
#define TC_OK 1
#else
#define TC_OK 0
#endif

// ---- shared memory layout (bytes, from dynamic smem base) ----
#define SM_TMEMPTR 0
#define SM_MB1     16
#define SM_MB2     24
#define SM_B       32          // 64 floats bias
#define SM_WH      1024        // W hi  [64k][256d] bf16 blocked-atom SW128  (32KB)
#define SM_WL      (SM_WH  + 32768)
#define SM_XTH     (SM_WL  + 32768)   // X^T hi [64n][256d]
#define SM_XTL     (SM_XTH + 32768)
#define SM_XDH     (SM_XTL + 32768)   // X hi [256d][64n]
#define SM_XDL     (SM_XDH + 32768)
#define SM_AH      (SM_XDL + 32768)   // a hi [64k][64n]  (8KB)
#define SM_AL      (SM_AH  + 8192)
#define SM_TOTAL   (SM_AL  + 8192)    // 214016 B

// idesc: kind::f16, dtype=F32, atype=btype=BF16, N=64, M=128
#define IDESC ((1u<<4) | (1u<<7) | (1u<<10) | (8u<<17) | (8u<<24))

#define SWZ(o) ((o) ^ (((o) >> 3) & 0x70))

// SW128 K-major descriptor base: layout=2, version=1, SBO=64, LBO=1
#define DESC_BASE 0x4000404000010000ULL

__device__ float g_V[Kc * Dc];
__device__ float g_asum[Kc];

// ------------------------- PTX helpers -------------------------
__device__ __forceinline__ uint32_t smem_u32(const void* p) {
    uint32_t a;
    asm("{ .reg .u64 t; cvta.to.shared.u64 t, %1; cvt.u32.u64 %0, t; }" : "=r"(a) : "l"(p));
    return a;
}
__device__ __forceinline__ uint64_t make_desc(uint32_t addr) {
    return DESC_BASE | ((uint64_t)(addr >> 4) & 0x3FFF);
}
#if TC_OK
__device__ __forceinline__ void mma_f16_ss(uint32_t d_tmem, uint64_t a_desc,
                                           uint64_t b_desc, uint32_t idesc, int acc) {
    asm volatile(
        "{\n\t.reg .pred p;\n\tsetp.ne.u32 p, %4, 0;\n\t"
        "tcgen05.mma.cta_group::1.kind::f16 [%0], %1, %2, %3, {%5, %5, %5, %5}, p;\n\t}"
        :: "r"(d_tmem), "l"(a_desc), "l"(b_desc), "r"(idesc), "r"((uint32_t)acc), "r"(0u)
        : "memory");
}
#endif
#define TC_COMMIT(mbar) \
    asm volatile("tcgen05.commit.cta_group::1.mbarrier::arrive::one.shared::cluster.b64 [%0];" \
                 :: "r"(mbar) : "memory")
#define TC_ALLOC(dst, n) \
    asm volatile("tcgen05.alloc.cta_group::1.sync.aligned.shared::cta.b32 [%0], %1;" \
                 :: "r"(dst), "r"(n) : "memory")
#define TC_RELINQ() asm volatile("tcgen05.relinquish_alloc_permit.cta_group::1.sync.aligned;")
#define TC_DEALLOC(base, n) \
    asm volatile("tcgen05.dealloc.cta_group::1.sync.aligned.b32 %0, %1;" :: "r"(base), "r"(n))
#define TC_WAIT_LD() asm volatile("tcgen05.wait::ld.sync.aligned;" ::: "memory")
#define TC_FENCE_AFTER() asm volatile("tcgen05.fence::after_thread_sync;" ::: "memory")
#define FENCE_ASYNC() asm volatile("fence.proxy.async.shared::cta;" ::: "memory")
#define MB_INIT(addr, cnt) \
    asm volatile("mbarrier.init.shared.b64 [%0], %1;" :: "r"(addr), "r"((uint32_t)(cnt)) : "memory")
#define MB_INVAL(addr) asm volatile("mbarrier.inval.shared.b64 [%0];" :: "r"(addr) : "memory")

#define MB_WAIT(mbar, ph) do {                                                  \
    uint32_t _m = (mbar); uint32_t _p = (uint32_t)(ph); uint32_t _done;         \
    asm volatile("{\n\t.reg .pred p;\n\t"                                       \
        "mbarrier.try_wait.parity.acquire.cta.shared::cta.b64 p, [%1], %2;\n\t" \
        "selp.b32 %0, 1, 0, p;\n\t}" : "=r"(_done) : "r"(_m), "r"(_p) : "memory"); \
    if (!_done) {                                                               \
        asm volatile("{\n\t.reg .pred P1;\n\t"                                  \
            "WL_%=:\n\t"                                                        \
            "mbarrier.try_wait.parity.acquire.cta.shared::cta.b64 P1, [%0], %1, 0x989680;\n\t" \
            "@P1 bra.uni WD_%=;\n\t"                                            \
            "bra.uni WL_%=;\n\t"                                                \
            "WD_%=:\n\t}" :: "r"(_m), "r"(_p) : "memory");                      \
    }                                                                           \
} while (0)

#define TC_LD_X32(r, addr)                                                      \
    asm volatile("tcgen05.ld.sync.aligned.32x32b.x32.b32 "                      \
        "{%0, %1, %2, %3, %4, %5, %6, %7, %8, %9, %10, %11, %12, %13, %14, %15, " \
        " %16, %17, %18, %19, %20, %21, %22, %23, %24, %25, %26, %27, %28, %29, %30, %31}, [%32];" \
        : "=r"((r)[0]),  "=r"((r)[1]),  "=r"((r)[2]),  "=r"((r)[3]),            \
          "=r"((r)[4]),  "=r"((r)[5]),  "=r"((r)[6]),  "=r"((r)[7]),            \
          "=r"((r)[8]),  "=r"((r)[9]),  "=r"((r)[10]), "=r"((r)[11]),           \
          "=r"((r)[12]), "=r"((r)[13]), "=r"((r)[14]), "=r"((r)[15]),           \
          "=r"((r)[16]), "=r"((r)[17]), "=r"((r)[18]), "=r"((r)[19]),           \
          "=r"((r)[20]), "=r"((r)[21]), "=r"((r)[22]), "=r"((r)[23]),           \
          "=r"((r)[24]), "=r"((r)[25]), "=r"((r)[26]), "=r"((r)[27]),           \
          "=r"((r)[28]), "=r"((r)[29]), "=r"((r)[30]), "=r"((r)[31])            \
        : "r"(addr))

__device__ __forceinline__ uint32_t pack2(__nv_bfloat16 a, __nv_bfloat16 b) {
    return (uint32_t)__bfloat16_as_ushort(a) | ((uint32_t)__bfloat16_as_ushort(b) << 16);
}
__device__ __forceinline__ void split2(float v, __nv_bfloat16& h, __nv_bfloat16& l) {
    h = __float2bfloat16_rn(v);
    l = __float2bfloat16_rn(v - __bfloat162float(h));
}

// ------------------------- kernels -------------------------
__global__ void zero_kernel() {
    int t = blockIdx.x * blockDim.x + threadIdx.x;
    if (t < Kc * Dc) g_V[t] = 0.0f;
    if (t < Kc) g_asum[t] = 0.0f;
}

__global__ __launch_bounds__(NTHREADS, 1) __cluster_dims__(1, 1, 1)
void netvlad_tc_kernel(const float* __restrict__ x,
                       const float* __restrict__ conv_w,
                       const float* __restrict__ conv_b,
                       int N, int numTiles) {
#if TC_OK
    extern __shared__ char smem[];
    const uint32_t sbase = smem_u32(smem);
    const int tid = threadIdx.x;
    const int wid = tid >> 5;

    // init
    if (tid == 0) { MB_INIT(sbase + SM_MB1, 1); MB_INIT(sbase + SM_MB2, 1); }
    if (wid == 0) { TC_ALLOC(sbase + SM_TMEMPTR, 256); TC_RELINQ(); }
    if (tid < Kc) *(float*)(smem + SM_B + tid * 4) = conv_b[tid];
    __syncthreads();
    uint32_t tmem;
    asm volatile("ld.shared.b32 %0, [%1];" : "=r"(tmem) : "r"(sbase + SM_TMEMPTR));

    // stage W hi/lo (blocked-atom SW128, K-major rows=k, cols=d, atom_rows=8)
    for (int i = tid; i < (Kc * Dc) / 4; i += NTHREADS) {
        int k = i >> 6;
        int d0 = (i & 63) * 4;
        float4 w4 = reinterpret_cast<const float4*>(conv_w)[i];
        __nv_bfloat16 h0, h1, h2, h3, l0, l1, l2, l3;
        split2(w4.x, h0, l0); split2(w4.y, h1, l1); split2(w4.z, h2, l2); split2(w4.w, h3, l3);
        uint32_t o = ((uint32_t)((k >> 3) + ((d0 >> 6) << 3)) << 10) + ((k & 7) << 7) + ((d0 & 63) << 1);
        o = SWZ(o);
        *(uint2*)(smem + SM_WH + o) = make_uint2(pack2(h0, h1), pack2(h2, h3));
        *(uint2*)(smem + SM_WL + o) = make_uint2(pack2(l0, l1), pack2(l2, l3));
    }

    // descriptors
    const uint64_t dWh  = make_desc(sbase + SM_WH);
    const uint64_t dWl  = make_desc(sbase + SM_WL);
    const uint64_t dXtH = make_desc(sbase + SM_XTH);
    const uint64_t dXtL = make_desc(sbase + SM_XTL);
    const uint64_t dXdH = make_desc(sbase + SM_XDH);
    const uint64_t dXdL = make_desc(sbase + SM_XDL);
    const uint64_t dAH  = make_desc(sbase + SM_AH);
    const uint64_t dAL  = make_desc(sbase + SM_AL);
    const float* sBf = (const float*)(smem + SM_B);

    // transpose-phase mapping: thread = (n-pair p, d-block b of 32 d's)
    const int pp   = tid & 31;
    const int bblk = tid >> 5;

    float asum_local = 0.0f;
    int ph1 = 0, ph2 = 0, cnt = 0;

    for (int tile = blockIdx.x; tile < numTiles; tile += gridDim.x, cnt++) {
        const int n0 = tile * TN;

        // ---- 1) stage loads from gmem into registers ----
        float4 v[16];
#pragma unroll
        for (int j = 0; j < 16; j++) {
            int i = tid + NTHREADS * j;
            int d = i >> 4, n4 = i & 15;
            v[j] = *(reinterpret_cast<const float4*>(x + (size_t)d * N + n0) + n4);
        }

        // ---- 2) wait prev GEMM2 (protects Xd/Xt/A), sync ----
        if (cnt > 0) { MB_WAIT(sbase + SM_MB2, ph2); ph2 ^= 1; }
        __syncthreads();

        // ---- 3a) convert + store Xd only (vectorized, conflict-free) ----
#pragma unroll
        for (int j = 0; j < 16; j++) {
            int i = tid + NTHREADS * j;
            int d = i >> 4;
            int n = (i & 15) * 4;
            float4 vv = v[j];
            __nv_bfloat16 h0, h1, h2, h3, l0, l1, l2, l3;
            split2(vv.x, h0, l0); split2(vv.y, h1, l1); split2(vv.z, h2, l2); split2(vv.w, h3, l3);
            uint32_t od = ((uint32_t)(d >> 3) << 10) + ((d & 7) << 7) + (n << 1);
            od = SWZ(od);
            *(uint2*)(smem + SM_XDH + od) = make_uint2(pack2(h0, h1), pack2(h2, h3));
            *(uint2*)(smem + SM_XDL + od) = make_uint2(pack2(l0, l1), pack2(l2, l3));
        }
        __syncthreads();

        // ---- 3b) build Xt[n][d] from Xd[d][n] via smem (LDS.32 + PRMT + STS.128) ----
#pragma unroll
        for (int pr = 0; pr < 2; pr++) {
            const int srcB = pr ? SM_XDL : SM_XDH;
            const int dstB = pr ? SM_XTL : SM_XTH;
#pragma unroll
            for (int g = 0; g < 4; g++) {
                const int d0 = bblk * 32 + g * 8;
                uint32_t u[8];
#pragma unroll
                for (int r = 0; r < 8; r++) {
                    int d = d0 + r;
                    uint32_t od = ((uint32_t)(d >> 3) << 10) + ((d & 7) << 7) + (pp << 2);
                    od = SWZ(od);
                    u[r] = *(const uint32_t*)(smem + srcB + od);
                }
                // even row n = 2*pp : low halves; odd row n = 2*pp+1 : high halves
                uint4 ev = make_uint4(__byte_perm(u[0], u[1], 0x5410),
                                      __byte_perm(u[2], u[3], 0x5410),
                                      __byte_perm(u[4], u[5], 0x5410),
                                      __byte_perm(u[6], u[7], 0x5410));
                uint4 od4 = make_uint4(__byte_perm(u[0], u[1], 0x7632),
                                       __byte_perm(u[2], u[3], 0x7632),
                                       __byte_perm(u[4], u[5], 0x7632),
                                       __byte_perm(u[6], u[7], 0x7632));
                int ne = 2 * pp, no = 2 * pp + 1;
                uint32_t oe = ((uint32_t)((ne >> 3) + ((d0 >> 6) << 3)) << 10) + ((ne & 7) << 7) + ((d0 & 63) << 1);
                oe = SWZ(oe);
                uint32_t oo = ((uint32_t)((no >> 3) + ((d0 >> 6) << 3)) << 10) + ((no & 7) << 7) + ((d0 & 63) << 1);
                oo = SWZ(oo);
                *(uint4*)(smem + dstB + oe) = ev;
                *(uint4*)(smem + dstB + oo) = od4;
            }
        }
        FENCE_ASYNC();
        __syncthreads();

        // ---- 4) GEMM1: D1[pix][k] = Xh*Wh + Xh*Wl + Xl*Wh ----
        if (tid == 0) {
#pragma unroll
            for (int t = 0; t < 3; t++) {
                uint64_t at = (t == 2) ? dXtL : dXtH;
                uint64_t bt = (t == 1) ? dWl : dWh;
#pragma unroll
                for (int s = 0; s < 16; s++) {
                    uint64_t off = (uint64_t)(((s >> 2) * 512) + ((s & 3) * 2));
                    mma_f16_ss(tmem, at + off, bt + off, IDESC, (t | s) != 0);
                }
            }
            TC_COMMIT(sbase + SM_MB1);
        }

        // ---- 5) softmax per pixel (lane = pixel), no max pass, 4-way sums ----
        if (tid < TN) {
            MB_WAIT(sbase + SM_MB1, ph1);
            TC_FENCE_AFTER();
            uint32_t au[64];
            TC_LD_X32(au, tmem);
            TC_LD_X32(au + 32, tmem + 32);
            TC_WAIT_LD();
            float s0 = 0.f, s1 = 0.f, s2 = 0.f, s3 = 0.f;
#pragma unroll
            for (int c = 0; c < 64; c += 4) {
                float e0 = __expf(__uint_as_float(au[c + 0]) + sBf[c + 0]);
                float e1 = __expf(__uint_as_float(au[c + 1]) + sBf[c + 1]);
                float e2 = __expf(__uint_as_float(au[c + 2]) + sBf[c + 2]);
                float e3 = __expf(__uint_as_float(au[c + 3]) + sBf[c + 3]);
                au[c + 0] = __float_as_uint(e0);
                au[c + 1] = __float_as_uint(e1);
                au[c + 2] = __float_as_uint(e2);
                au[c + 3] = __float_as_uint(e3);
                s0 += e0; s1 += e1; s2 += e2; s3 += e3;
            }
            float rinv = 1.0f / ((s0 + s1) + (s2 + s3));
#pragma unroll
            for (int c = 0; c < 64; c++) {
                float aa = __uint_as_float(au[c]) * rinv;
                __nv_bfloat16 h, l;
                split2(aa, h, l);
                uint32_t o = ((uint32_t)(c >> 3) << 10) + ((c & 7) << 7) + (tid << 1);
                o = SWZ(o);
                *(__nv_bfloat16*)(smem + SM_AH + o) = h;
                *(__nv_bfloat16*)(smem + SM_AL + o) = l;
            }
            FENCE_ASYNC();
        }
        ph1 ^= 1;
        __syncthreads();

        // ---- 6) GEMM2: D2[d][k] += Xd*a^T (3 split terms, 2 d-halves) ----
        if (tid == 0) {
#pragma unroll
            for (int h = 0; h < 2; h++) {
#pragma unroll
                for (int t = 0; t < 3; t++) {
                    uint64_t at = ((t == 1) ? dXdL : dXdH) + (uint64_t)(h * 1024);
                    uint64_t bt = (t == 2) ? dAL : dAH;
#pragma unroll
                    for (int s = 0; s < 4; s++) {
                        int acc = !(cnt == 0 && t == 0 && s == 0);
                        mma_f16_ss(tmem + 64 + 64 * h, at + (uint64_t)(s * 2), bt + (uint64_t)(s * 2), IDESC, acc);
                    }
                }
            }
            TC_COMMIT(sbase + SM_MB2);
        }

        // ---- 7) asum[k] partial: sum row k of stored a (hi+lo); overlaps MMA ----
        if (tid < Kc) {
            uint32_t rb = ((uint32_t)(tid >> 3) << 10) + ((tid & 7) << 7);
            float s = 0.0f;
#pragma unroll
            for (int j = 0; j < 8; j++) {
                uint4 uh = *(const uint4*)(smem + SM_AH + rb + 16 * j);
                uint4 ul = *(const uint4*)(smem + SM_AL + rb + 16 * j);
                float2 f;
                f = __bfloat1622float2(*(__nv_bfloat162*)&uh.x); s += f.x + f.y;
                f = __bfloat1622float2(*(__nv_bfloat162*)&uh.y); s += f.x + f.y;
                f = __bfloat1622float2(*(__nv_bfloat162*)&uh.z); s += f.x + f.y;
                f = __bfloat1622float2(*(__nv_bfloat162*)&uh.w); s += f.x + f.y;
                f = __bfloat1622float2(*(__nv_bfloat162*)&ul.x); s += f.x + f.y;
                f = __bfloat1622float2(*(__nv_bfloat162*)&ul.y); s += f.x + f.y;
                f = __bfloat1622float2(*(__nv_bfloat162*)&ul.z); s += f.x + f.y;
                f = __bfloat1622float2(*(__nv_bfloat162*)&ul.w); s += f.x + f.y;
            }
            asum_local += s;
        }
    }

    // ---- final flush ----
    if (cnt > 0) {
        MB_WAIT(sbase + SM_MB2, ph2); ph2 ^= 1;
        TC_FENCE_AFTER();
        uint32_t r[64];
        uint32_t cbase = tmem + 64 + ((tid >= 128) ? 64 : 0);
        TC_LD_X32(r, cbase);
        TC_LD_X32(r + 32, cbase + 32);
        TC_WAIT_LD();
#pragma unroll
        for (int c = 0; c < 64; c++)
            atomicAdd(&g_V[c * Dc + tid], __uint_as_float(r[c]));
        if (tid < Kc) atomicAdd(&g_asum[tid], asum_local);
    }
    __syncthreads();
    if (tid == 0) { MB_INVAL(sbase + SM_MB1); MB_INVAL(sbase + SM_MB2); }
    __syncthreads();
    if (wid == 0) TC_DEALLOC(tmem, 256);
#else
    // ---------- FFMA fallback (correct on non-a targets; never the fast path) ----------
    extern __shared__ float fsm[];
    float* sW  = fsm;                  // [64][257]
    float* sXT = sW + Kc * 257;        // [64][257]
    float* sA  = sXT + TN * 257;       // [64][65]
    float* sB  = sA + Kc * 65;         // [64]
    const int tid = threadIdx.x;
    for (int i = tid; i < (Kc * Dc) / 4; i += NTHREADS) {
        int k = (i * 4) / Dc, d = (i * 4) % Dc;
        float4 w4 = reinterpret_cast<const float4*>(conv_w)[i];
        float* p = &sW[k * 257 + d];
        p[0] = w4.x; p[1] = w4.y; p[2] = w4.z; p[3] = w4.w;
    }
    if (tid < Kc) sB[tid] = conv_b[tid];
    const int tn = tid & 15, tk = tid >> 4;
    const int td = tid & 31, tk2 = tid >> 5;
    float vacc[8][8];
#pragma unroll
    for (int i = 0; i < 8; i++)
#pragma unroll
        for (int j = 0; j < 8; j++) vacc[i][j] = 0.0f;
    float asum_acc = 0.0f;
    for (int tile = blockIdx.x; tile < numTiles; tile += gridDim.x) {
        const int n0 = tile * TN;
        __syncthreads();
        for (int i = tid; i < (Dc * TN) / 4; i += NTHREADS) {
            int d = i >> 4, ng = i & 15;
            float4 v = reinterpret_cast<const float4*>(x + (size_t)d * N + n0)[ng];
            int nb = ng * 4;
            sXT[(nb + 0) * 257 + d] = v.x; sXT[(nb + 1) * 257 + d] = v.y;
            sXT[(nb + 2) * 257 + d] = v.z; sXT[(nb + 3) * 257 + d] = v.w;
        }
        __syncthreads();
        float acc[4][4];
#pragma unroll
        for (int i = 0; i < 4; i++)
#pragma unroll
            for (int j = 0; j < 4; j++) acc[i][j] = 0.0f;
#pragma unroll 4
        for (int d = 0; d < Dc; d++) {
            float wv[4], xv[4];
#pragma unroll
            for (int i = 0; i < 4; i++) wv[i] = sW[(tk * 4 + i) * 257 + d];
#pragma unroll
            for (int j = 0; j < 4; j++) xv[j] = sXT[(tn * 4 + j) * 257 + d];
#pragma unroll
            for (int i = 0; i < 4; i++)
#pragma unroll
                for (int j = 0; j < 4; j++) acc[i][j] += wv[i] * xv[j];
        }
#pragma unroll
        for (int i = 0; i < 4; i++) {
            float b = sB[tk * 4 + i];
#pragma unroll
            for (int j = 0; j < 4; j++)
                sA[(tk * 4 + i) * 65 + (tn * 4 + j)] = acc[i][j] + b;
        }
        __syncthreads();
        if (tid < TN) {
            const int n = tid;
            float m = -1e30f;
            for (int k = 0; k < Kc; k++) m = fmaxf(m, sA[k * 65 + n]);
            float s = 0.0f;
            for (int k = 0; k < Kc; k++) {
                float e = __expf(sA[k * 65 + n] - m);
                sA[k * 65 + n] = e; s += e;
            }
            float r = 1.0f / s;
            for (int k = 0; k < Kc; k++) sA[k * 65 + n] *= r;
        }
        __syncthreads();
        if (tid < Kc) {
            float s = 0.0f;
            for (int n = 0; n < TN; n++) s += sA[tid * 65 + n];
            asum_acc += s;
        }
#pragma unroll 2
        for (int n = 0; n < TN; n++) {
            float av[8], xv[8];
#pragma unroll
            for (int i = 0; i < 8; i++) av[i] = sA[(tk2 * 8 + i) * 65 + n];
#pragma unroll
            for (int j = 0; j < 8; j++) xv[j] = sXT[n * 257 + td + 32 * j];
#pragma unroll
            for (int i = 0; i < 8; i++)
#pragma unroll
                for (int j = 0; j < 8; j++) vacc[i][j] += av[i] * xv[j];
        }
    }
#pragma unroll
    for (int i = 0; i < 8; i++)
#pragma unroll
        for (int j = 0; j < 8; j++)
            atomicAdd(&g_V[(tk2 * 8 + i) * Dc + td + 32 * j], vacc[i][j]);
    if (tid < Kc) atomicAdd(&g_asum[tid], asum_acc);
#endif
}

#define SW_STRIDE 257
__global__ void finalize_kernel(const float* __restrict__ c,
                                float* __restrict__ out) {
    extern __shared__ float fsm2[];
    float* sV = fsm2;                     // [64][257]
    float* sAs = sV + Kc * SW_STRIDE;     // [64]
    const int tid = threadIdx.x;          // 256 threads
    if (tid < Kc) sAs[tid] = g_asum[tid];
    __syncthreads();
    const int d = tid;
    float ss = 0.0f;
    for (int k = 0; k < Kc; k++) {
        float v = g_V[k * Dc + d] - c[k * Dc + d] * sAs[k];
        sV[k * SW_STRIDE + d] = v;
        ss += v * v;
    }
    float r = 1.0f / fmaxf(sqrtf(ss), 1e-12f);
    for (int k = 0; k < Kc; k++) sV[k * SW_STRIDE + d] *= r;
    __syncthreads();
    if (tid < Kc) {
        const int k = tid;
        float rs = 0.0f;
        for (int dd = 0; dd < Dc; dd++) {
            float v = sV[k * SW_STRIDE + dd];
            rs += v * v;
        }
        float rr = 1.0f / fmaxf(sqrtf(rs), 1e-12f);
        for (int dd = 0; dd < Dc; dd++)
            out[k * Dc + dd] = sV[k * SW_STRIDE + dd] * rr;
    }
}

extern "C" void kernel_launch(void* const* d_in, const int* in_sizes, int n_in,
                              void* d_out, int out_size) {
    const float* x      = (const float*)d_in[0];
    const float* c      = (const float*)d_in[1];
    const float* conv_w = (const float*)d_in[2];
    const float* conv_b = (const float*)d_in[3];
    float* out = (float*)d_out;

    const int N = in_sizes[0] / Dc;
    const int numTiles = N / TN;

    int nsm = 148;
    cudaDeviceGetAttribute(&nsm, cudaDevAttrMultiProcessorCount, 0);

    cudaFuncSetAttribute(netvlad_tc_kernel,
                         cudaFuncAttributeMaxDynamicSharedMemorySize, SM_TOTAL);
    const int fin_smem = (Kc * SW_STRIDE + Kc) * (int)sizeof(float);
    cudaFuncSetAttribute(finalize_kernel,
                         cudaFuncAttributeMaxDynamicSharedMemorySize, fin_smem);

    zero_kernel<<<(Kc * Dc + 255) / 256, 256>>>();
    netvlad_tc_kernel<<<nsm, NTHREADS, SM_TOTAL>>>(x, conv_w, conv_b, N, numTiles);
    finalize_kernel<<<1, 256, fin_smem>>>(c, out);
}

// round 7
// speedup vs baseline: 1.7369x; 1.2690x over previous
#include <cuda_runtime.h>
#include <cuda_bf16.h>
#include <stdint.h>
#include <math.h>

#define Dc 256
#define Kc 64
#define TN 64
#define NTHREADS 256

#if defined(__CUDA_ARCH_FEAT_SM103_ALL) || defined(__CUDA_ARCH_FEAT_SM100_ALL)
#define TC_OK 1
#else
#define TC_OK 0
#endif

// ---- shared memory layout (bytes, from dynamic smem base) ----
#define SM_TMEMPTR 0
#define SM_MB1     16
#define SM_MB2     24
#define SM_B       32                   // 64 floats bias
#define SM_SCRP    512                  // 128 floats partial sums (w*32+lane)
#define SM_SCRR    1024                 // 64 floats rinv
#define SM_WH      2048                 // W hi [128 k2][256 d] bf16 SW128 blocked (64KB)
#define SM_WL      (SM_WH  + 65536)
#define SM_XDH     (SM_WL  + 65536)     // X hi [256 d][64 n]  (32KB)
#define SM_XDL     (SM_XDH + 32768)
#define SM_AH      (SM_XDL + 32768)     // a hi [64 k][64 n]   (8KB)
#define SM_AL      (SM_AH  + 8192)
#define SM_TOTAL   (SM_AL  + 8192)      // 215040 B

// idesc: kind::f16, dtype=F32, atype=btype=BF16, N=64, M=128
#define IDESC  ((1u<<4) | (1u<<7) | (1u<<10) | (8u<<17) | (8u<<24))
#define IDESC1 (IDESC | (1u<<16))       // + b_major (B is MN-major)

#define SWZ(o) ((o) ^ (((o) >> 3) & 0x70))

// SW128 descriptor: layout=2, version=1, SBO=64 (1024B atom stride), LBO=1.
// For swizzled layouts LBO is implicit in the atom; SBO is the stride between
// 8-row core-matrix groups in the strided dim — SAME for K-major and MN-major.
// The b_major idesc bit carries the transpose, not the descriptor fields.
#define DESC_BASE    0x4000404000010000ULL

__device__ float g_V[Kc * Dc];
__device__ float g_asum[Kc];

// ------------------------- PTX helpers -------------------------
__device__ __forceinline__ uint32_t smem_u32(const void* p) {
    uint32_t a;
    asm("{ .reg .u64 t; cvta.to.shared.u64 t, %1; cvt.u32.u64 %0, t; }" : "=r"(a) : "l"(p));
    return a;
}
__device__ __forceinline__ uint64_t make_desc(uint32_t addr) {
    return DESC_BASE | ((uint64_t)(addr >> 4) & 0x3FFF);
}
#if TC_OK
__device__ __forceinline__ void mma_f16_ss(uint32_t d_tmem, uint64_t a_desc,
                                           uint64_t b_desc, uint32_t idesc, int acc) {
    asm volatile(
        "{\n\t.reg .pred p;\n\tsetp.ne.u32 p, %4, 0;\n\t"
        "tcgen05.mma.cta_group::1.kind::f16 [%0], %1, %2, %3, {%5, %5, %5, %5}, p;\n\t}"
        :: "r"(d_tmem), "l"(a_desc), "l"(b_desc), "r"(idesc), "r"((uint32_t)acc), "r"(0u)
        : "memory");
}
#endif
#define TC_COMMIT(mbar) \
    asm volatile("tcgen05.commit.cta_group::1.mbarrier::arrive::one.shared::cluster.b64 [%0];" \
                 :: "r"(mbar) : "memory")
#define TC_ALLOC(dst, n) \
    asm volatile("tcgen05.alloc.cta_group::1.sync.aligned.shared::cta.b32 [%0], %1;" \
                 :: "r"(dst), "r"(n) : "memory")
#define TC_RELINQ() asm volatile("tcgen05.relinquish_alloc_permit.cta_group::1.sync.aligned;")
#define TC_DEALLOC(base, n) \
    asm volatile("tcgen05.dealloc.cta_group::1.sync.aligned.b32 %0, %1;" :: "r"(base), "r"(n))
#define TC_WAIT_LD() asm volatile("tcgen05.wait::ld.sync.aligned;" ::: "memory")
#define TC_FENCE_AFTER() asm volatile("tcgen05.fence::after_thread_sync;" ::: "memory")
#define TC_FENCE_BEFORE() asm volatile("tcgen05.fence::before_thread_sync;" ::: "memory")
#define FENCE_ASYNC() asm volatile("fence.proxy.async.shared::cta;" ::: "memory")
#define MB_INIT(addr, cnt) \
    asm volatile("mbarrier.init.shared.b64 [%0], %1;" :: "r"(addr), "r"((uint32_t)(cnt)) : "memory")
#define MB_INVAL(addr) asm volatile("mbarrier.inval.shared.b64 [%0];" :: "r"(addr) : "memory")

#define MB_WAIT(mbar, ph) do {                                                  \
    uint32_t _m = (mbar); uint32_t _p = (uint32_t)(ph); uint32_t _done;         \
    asm volatile("{\n\t.reg .pred p;\n\t"                                       \
        "mbarrier.try_wait.parity.acquire.cta.shared::cta.b64 p, [%1], %2;\n\t" \
        "selp.b32 %0, 1, 0, p;\n\t}" : "=r"(_done) : "r"(_m), "r"(_p) : "memory"); \
    if (!_done) {                                                               \
        asm volatile("{\n\t.reg .pred P1;\n\t"                                  \
            "WL_%=:\n\t"                                                        \
            "mbarrier.try_wait.parity.acquire.cta.shared::cta.b64 P1, [%0], %1, 0x989680;\n\t" \
            "@P1 bra.uni WD_%=;\n\t"                                            \
            "bra.uni WL_%=;\n\t"                                                \
            "WD_%=:\n\t}" :: "r"(_m), "r"(_p) : "memory");                      \
    }                                                                           \
} while (0)

#define TC_LD_X32(r, addr)                                                      \
    asm volatile("tcgen05.ld.sync.aligned.32x32b.x32.b32 "                      \
        "{%0, %1, %2, %3, %4, %5, %6, %7, %8, %9, %10, %11, %12, %13, %14, %15, " \
        " %16, %17, %18, %19, %20, %21, %22, %23, %24, %25, %26, %27, %28, %29, %30, %31}, [%32];" \
        : "=r"((r)[0]),  "=r"((r)[1]),  "=r"((r)[2]),  "=r"((r)[3]),            \
          "=r"((r)[4]),  "=r"((r)[5]),  "=r"((r)[6]),  "=r"((r)[7]),            \
          "=r"((r)[8]),  "=r"((r)[9]),  "=r"((r)[10]), "=r"((r)[11]),           \
          "=r"((r)[12]), "=r"((r)[13]), "=r"((r)[14]), "=r"((r)[15]),           \
          "=r"((r)[16]), "=r"((r)[17]), "=r"((r)[18]), "=r"((r)[19]),           \
          "=r"((r)[20]), "=r"((r)[21]), "=r"((r)[22]), "=r"((r)[23]),           \
          "=r"((r)[24]), "=r"((r)[25]), "=r"((r)[26]), "=r"((r)[27]),           \
          "=r"((r)[28]), "=r"((r)[29]), "=r"((r)[30]), "=r"((r)[31])            \
        : "r"(addr))

__device__ __forceinline__ uint32_t b2u(__nv_bfloat162 v) {
    return *(uint32_t*)&v;
}

// ------------------------- kernels -------------------------
__global__ void zero_kernel() {
    int t = blockIdx.x * blockDim.x + threadIdx.x;
    if (t < Kc * Dc) g_V[t] = 0.0f;
    if (t < Kc) g_asum[t] = 0.0f;
}

__global__ __launch_bounds__(NTHREADS, 1) __cluster_dims__(1, 1, 1)
void netvlad_tc_kernel(const float* __restrict__ x,
                       const float* __restrict__ conv_w,
                       const float* __restrict__ conv_b,
                       int N, int numTiles) {
#if TC_OK
    extern __shared__ char smem[];
    const uint32_t sbase = smem_u32(smem);
    const int tid  = threadIdx.x;
    const int wid  = tid >> 5;
    const int lane = tid & 31;

    // init
    if (tid == 0) { MB_INIT(sbase + SM_MB1, 1); MB_INIT(sbase + SM_MB2, 1); }
    if (wid == 0) { TC_ALLOC(sbase + SM_TMEMPTR, 256); TC_RELINQ(); }
    if (tid < Kc) *(float*)(smem + SM_B + tid * 4) = conv_b[tid];
    __syncthreads();
    uint32_t tmem;
    asm volatile("ld.shared.b32 %0, [%1];" : "=r"(tmem) : "r"(sbase + SM_TMEMPTR));

    // stage W hi/lo, M=128 (rows 64-127 = copy of rows 0-63). Blocked SW128:
    // atom = (k>>3) + (d>>6)*16; 16 atom-rows x 4 atom-cols.
    for (int i = tid; i < (Kc * Dc) / 4; i += NTHREADS) {
        int k = i >> 6;
        int d0 = (i & 63) * 4;
        float4 w4 = reinterpret_cast<const float4*>(conv_w)[i];
        __nv_bfloat162 h0 = __float22bfloat162_rn(make_float2(w4.x, w4.y));
        __nv_bfloat162 h1 = __float22bfloat162_rn(make_float2(w4.z, w4.w));
        float2 f0 = __bfloat1622float2(h0), f1 = __bfloat1622float2(h1);
        __nv_bfloat162 l0 = __float22bfloat162_rn(make_float2(w4.x - f0.x, w4.y - f0.y));
        __nv_bfloat162 l1 = __float22bfloat162_rn(make_float2(w4.z - f1.x, w4.w - f1.y));
        uint32_t o = ((uint32_t)((k >> 3) + ((d0 >> 6) << 4)) << 10) + ((k & 7) << 7) + ((d0 & 63) << 1);
        o = SWZ(o);
        uint2 hv = make_uint2(b2u(h0), b2u(h1));
        uint2 lv = make_uint2(b2u(l0), b2u(l1));
        *(uint2*)(smem + SM_WH + o) = hv;
        *(uint2*)(smem + SM_WH + o + 8192) = hv;   // k+64 copy (atom +8)
        *(uint2*)(smem + SM_WL + o) = lv;
        *(uint2*)(smem + SM_WL + o + 8192) = lv;
    }

    // descriptors (MN-major B uses the SAME physical descriptor; b_major bit
    // in the idesc carries the transpose)
    const uint64_t dWh    = make_desc(sbase + SM_WH);
    const uint64_t dWl    = make_desc(sbase + SM_WL);
    const uint64_t dXdHmn = make_desc(sbase + SM_XDH);   // GEMM1 B (b_major)
    const uint64_t dXdLmn = make_desc(sbase + SM_XDL);
    const uint64_t dXdH   = make_desc(sbase + SM_XDH);   // GEMM2 A (K-major)
    const uint64_t dXdL   = make_desc(sbase + SM_XDL);
    const uint64_t dAH    = make_desc(sbase + SM_AH);
    const uint64_t dAL    = make_desc(sbase + SM_AL);
    const float* sBf  = (const float*)(smem + SM_B);
    float* scrP = (float*)(smem + SM_SCRP);
    float* scrR = (float*)(smem + SM_SCRR);

    // softmax mapping: warps 0-3; k = (w&1)*32+lane; n-half = w>>1
    const int kk = ((wid & 1) << 5) + lane;
    const int nh = (wid >> 1) & 1;
    const float bk = (wid < 4) ? sBf[kk] : 0.0f;

    float asum_local = 0.0f;
    int ph1 = 0, ph2 = 0, cnt = 0;

    for (int tile = blockIdx.x; tile < numTiles; tile += gridDim.x, cnt++) {
        const int n0 = tile * TN;

        // ---- 1) prefetch gmem tile into registers ----
        float4 v[16];
#pragma unroll
        for (int j = 0; j < 16; j++) {
            int i = tid + NTHREADS * j;
            int d = i >> 4, n4 = i & 15;
            v[j] = *(reinterpret_cast<const float4*>(x + (size_t)d * N + n0) + n4);
        }

        // ---- 2) wait prev GEMM2 (protects Xd & A) ----
        if (cnt > 0) { MB_WAIT(sbase + SM_MB2, ph2); ph2 ^= 1; }
        __syncthreads();

        // ---- 3) convert + store Xd hi/lo (vectorized, conflict-free) ----
#pragma unroll
        for (int j = 0; j < 16; j++) {
            int i = tid + NTHREADS * j;
            int d = i >> 4;
            int n = (i & 15) * 4;
            float4 vv = v[j];
            __nv_bfloat162 h0 = __float22bfloat162_rn(make_float2(vv.x, vv.y));
            __nv_bfloat162 h1 = __float22bfloat162_rn(make_float2(vv.z, vv.w));
            float2 f0 = __bfloat1622float2(h0), f1 = __bfloat1622float2(h1);
            __nv_bfloat162 l0 = __float22bfloat162_rn(make_float2(vv.x - f0.x, vv.y - f0.y));
            __nv_bfloat162 l1 = __float22bfloat162_rn(make_float2(vv.z - f1.x, vv.w - f1.y));
            uint32_t od = ((uint32_t)(d >> 3) << 10) + ((d & 7) << 7) + (n << 1);
            od = SWZ(od);
            *(uint2*)(smem + SM_XDH + od) = make_uint2(b2u(h0), b2u(h1));
            *(uint2*)(smem + SM_XDL + od) = make_uint2(b2u(l0), b2u(l1));
        }
        FENCE_ASYNC();
        __syncthreads();

        // ---- 4) GEMM1: D1[k2][n] = W*Xd  (A=W K-major, B=Xd MN-major/b_major) ----
        if (tid == 0) {
#pragma unroll
            for (int t = 0; t < 3; t++) {
                uint64_t at = (t == 1) ? dWl : dWh;
                uint64_t bt = (t == 2) ? dXdLmn : dXdHmn;
#pragma unroll
                for (int s = 0; s < 16; s++) {
                    uint64_t ao = (uint64_t)(((s >> 2) * 1024) + ((s & 3) * 2));
                    uint64_t bo = (uint64_t)(s * 128);
                    mma_f16_ss(tmem, at + ao, bt + bo, IDESC1, (t | s) != 0);
                }
            }
            TC_COMMIT(sbase + SM_MB1);
        }

        // ---- 5) softmax: 4 warps, lane=k, regs hold 32 n-values ----
        uint32_t au[32];
        float sr[32];
        if (wid < 4) {
            MB_WAIT(sbase + SM_MB1, ph1);
            TC_FENCE_AFTER();
            TC_LD_X32(au, tmem + nh * 32);
            TC_WAIT_LD();
            TC_FENCE_BEFORE();
#pragma unroll
            for (int j = 0; j < 32; j++)
                sr[j] = __expf(__uint_as_float(au[j]) + bk);
            // fold-reduce: after 5 steps lane l holds sum over 32 k-lanes for n=nh*32+l
#pragma unroll
            for (int off = 16; off > 0; off >>= 1) {
#pragma unroll
                for (int j = 0; j < 16; j++) {
                    if (j < off) {
                        float x0 = sr[j], x1 = sr[off + j];
                        float mine = (lane & off) ? x1 : x0;
                        float send = (lane & off) ? x0 : x1;
                        float theirs = __shfl_xor_sync(0xffffffffu, send, off);
                        sr[j] = mine + theirs;
                    }
                }
            }
            scrP[wid * 32 + lane] = sr[0];
        }
        __syncthreads();
        if (wid < 4) {
            float tot = sr[0] + scrP[(wid ^ 1) * 32 + lane];
            scrR[nh * 32 + lane] = 1.0f / tot;   // dup write by warp pair: same value
        }
        __syncthreads();
        if (wid < 4) {
            const float* rsc = scrR + nh * 32;
            float as = 0.0f;
#pragma unroll
            for (int q = 0; q < 4; q++) {
                uint32_t hv[4], lv[4];
#pragma unroll
                for (int r = 0; r < 4; r++) {
                    int j = q * 8 + r * 2;
                    float a0 = __expf(__uint_as_float(au[j]) + bk) * rsc[j];
                    float a1 = __expf(__uint_as_float(au[j + 1]) + bk) * rsc[j + 1];
                    as += a0 + a1;
                    __nv_bfloat162 h2 = __float22bfloat162_rn(make_float2(a0, a1));
                    float2 f2 = __bfloat1622float2(h2);
                    __nv_bfloat162 l2 = __float22bfloat162_rn(make_float2(a0 - f2.x, a1 - f2.y));
                    hv[r] = b2u(h2); lv[r] = b2u(l2);
                }
                uint32_t o = ((uint32_t)(kk >> 3) << 10) + ((kk & 7) << 7) + ((uint32_t)(nh * 32 + q * 8) << 1);
                o = SWZ(o);
                *(uint4*)(smem + SM_AH + o) = make_uint4(hv[0], hv[1], hv[2], hv[3]);
                *(uint4*)(smem + SM_AL + o) = make_uint4(lv[0], lv[1], lv[2], lv[3]);
            }
            asum_local += as;
            FENCE_ASYNC();
        }
        ph1 ^= 1;
        __syncthreads();

        // ---- 6) GEMM2: D2[d][k] += Xd * a^T  (A=Xd K-major, B=a K-major) ----
        if (tid == 0) {
#pragma unroll
            for (int h = 0; h < 2; h++) {
#pragma unroll
                for (int t = 0; t < 3; t++) {
                    uint64_t at = ((t == 1) ? dXdL : dXdH) + (uint64_t)(h * 1024);
                    uint64_t bt = (t == 2) ? dAL : dAH;
#pragma unroll
                    for (int s = 0; s < 4; s++) {
                        int acc = !(cnt == 0 && t == 0 && s == 0);
                        mma_f16_ss(tmem + 64 + 64 * h, at + (uint64_t)(s * 2), bt + (uint64_t)(s * 2), IDESC, acc);
                    }
                }
            }
            TC_COMMIT(sbase + SM_MB2);
        }
    }

    // ---- final flush ----
    if (cnt > 0) {
        MB_WAIT(sbase + SM_MB2, ph2); ph2 ^= 1;
        TC_FENCE_AFTER();
        uint32_t r[64];
        uint32_t cbase = tmem + 64 + ((tid >= 128) ? 64 : 0);
        TC_LD_X32(r, cbase);
        TC_LD_X32(r + 32, cbase + 32);
        TC_WAIT_LD();
#pragma unroll
        for (int c = 0; c < 64; c++)
            atomicAdd(&g_V[c * Dc + tid], __uint_as_float(r[c]));
        if (wid < 4) atomicAdd(&g_asum[kk], asum_local);
    }
    __syncthreads();
    if (tid == 0) { MB_INVAL(sbase + SM_MB1); MB_INVAL(sbase + SM_MB2); }
    __syncthreads();
    if (wid == 0) TC_DEALLOC(tmem, 256);
#else
    // ---------- FFMA fallback (correct on non-a targets; never the fast path) ----------
    extern __shared__ float fsm[];
    float* sW  = fsm;                  // [64][257]
    float* sXT = sW + Kc * 257;        // [64][257]
    float* sA  = sXT + TN * 257;       // [64][65]
    float* sB  = sA + Kc * 65;         // [64]
    const int tid = threadIdx.x;
    for (int i = tid; i < (Kc * Dc) / 4; i += NTHREADS) {
        int k = (i * 4) / Dc, d = (i * 4) % Dc;
        float4 w4 = reinterpret_cast<const float4*>(conv_w)[i];
        float* p = &sW[k * 257 + d];
        p[0] = w4.x; p[1] = w4.y; p[2] = w4.z; p[3] = w4.w;
    }
    if (tid < Kc) sB[tid] = conv_b[tid];
    const int tn = tid & 15, tk = tid >> 4;
    const int td = tid & 31, tk2 = tid >> 5;
    float vacc[8][8];
#pragma unroll
    for (int i = 0; i < 8; i++)
#pragma unroll
        for (int j = 0; j < 8; j++) vacc[i][j] = 0.0f;
    float asum_acc = 0.0f;
    for (int tile = blockIdx.x; tile < numTiles; tile += gridDim.x) {
        const int n0 = tile * TN;
        __syncthreads();
        for (int i = tid; i < (Dc * TN) / 4; i += NTHREADS) {
            int d = i >> 4, ng = i & 15;
            float4 v = reinterpret_cast<const float4*>(x + (size_t)d * N + n0)[ng];
            int nb = ng * 4;
            sXT[(nb + 0) * 257 + d] = v.x; sXT[(nb + 1) * 257 + d] = v.y;
            sXT[(nb + 2) * 257 + d] = v.z; sXT[(nb + 3) * 257 + d] = v.w;
        }
        __syncthreads();
        float acc[4][4];
#pragma unroll
        for (int i = 0; i < 4; i++)
#pragma unroll
            for (int j = 0; j < 4; j++) acc[i][j] = 0.0f;
#pragma unroll 4
        for (int d = 0; d < Dc; d++) {
            float wv[4], xv[4];
#pragma unroll
            for (int i = 0; i < 4; i++) wv[i] = sW[(tk * 4 + i) * 257 + d];
#pragma unroll
            for (int j = 0; j < 4; j++) xv[j] = sXT[(tn * 4 + j) * 257 + d];
#pragma unroll
            for (int i = 0; i < 4; i++)
#pragma unroll
                for (int j = 0; j < 4; j++) acc[i][j] += wv[i] * xv[j];
        }
#pragma unroll
        for (int i = 0; i < 4; i++) {
            float b = sB[tk * 4 + i];
#pragma unroll
            for (int j = 0; j < 4; j++)
                sA[(tk * 4 + i) * 65 + (tn * 4 + j)] = acc[i][j] + b;
        }
        __syncthreads();
        if (tid < TN) {
            const int n = tid;
            float m = -1e30f;
            for (int k = 0; k < Kc; k++) m = fmaxf(m, sA[k * 65 + n]);
            float s = 0.0f;
            for (int k = 0; k < Kc; k++) {
                float e = __expf(sA[k * 65 + n] - m);
                sA[k * 65 + n] = e; s += e;
            }
            float r = 1.0f / s;
            for (int k = 0; k < Kc; k++) sA[k * 65 + n] *= r;
        }
        __syncthreads();
        if (tid < Kc) {
            float s = 0.0f;
            for (int n = 0; n < TN; n++) s += sA[tid * 65 + n];
            asum_acc += s;
        }
#pragma unroll 2
        for (int n = 0; n < TN; n++) {
            float av[8], xv[8];
#pragma unroll
            for (int i = 0; i < 8; i++) av[i] = sA[(tk2 * 8 + i) * 65 + n];
#pragma unroll
            for (int j = 0; j < 8; j++) xv[j] = sXT[n * 257 + td + 32 * j];
#pragma unroll
            for (int i = 0; i < 8; i++)
#pragma unroll
                for (int j = 0; j < 8; j++) vacc[i][j] += av[i] * xv[j];
        }
    }
#pragma unroll
    for (int i = 0; i < 8; i++)
#pragma unroll
        for (int j = 0; j < 8; j++)
            atomicAdd(&g_V[(tk2 * 8 + i) * Dc + td + 32 * j], vacc[i][j]);
    if (tid < Kc) atomicAdd(&g_asum[tid], asum_acc);
#endif
}

#define SW_STRIDE 257
__global__ void finalize_kernel(const float* __restrict__ c,
                                float* __restrict__ out) {
    extern __shared__ float fsm2[];
    float* sV = fsm2;                     // [64][257]
    float* sAs = sV + Kc * SW_STRIDE;     // [64]
    const int tid = threadIdx.x;          // 256 threads
    if (tid < Kc) sAs[tid] = g_asum[tid];
    __syncthreads();
    const int d = tid;
    float ss = 0.0f;
    for (int k = 0; k < Kc; k++) {
        float v = g_V[k * Dc + d] - c[k * Dc + d] * sAs[k];
        sV[k * SW_STRIDE + d] = v;
        ss += v * v;
    }
    float r = 1.0f / fmaxf(sqrtf(ss), 1e-12f);
    for (int k = 0; k < Kc; k++) sV[k * SW_STRIDE + d] *= r;
    __syncthreads();
    if (tid < Kc) {
        const int k = tid;
        float rs = 0.0f;
        for (int dd = 0; dd < Dc; dd++) {
            float v = sV[k * SW_STRIDE + dd];
            rs += v * v;
        }
        float rr = 1.0f / fmaxf(sqrtf(rs), 1e-12f);
        for (int dd = 0; dd < Dc; dd++)
            out[k * Dc + dd] = sV[k * SW_STRIDE + dd] * rr;
    }
}

extern "C" void kernel_launch(void* const* d_in, const int* in_sizes, int n_in,
                              void* d_out, int out_size) {
    const float* x      = (const float*)d_in[0];
    const float* c      = (const float*)d_in[1];
    const float* conv_w = (const float*)d_in[2];
    const float* conv_b = (const float*)d_in[3];
    float* out = (float*)d_out;

    const int N = in_sizes[0] / Dc;
    const int numTiles = N / TN;

    int nsm = 148;
    cudaDeviceGetAttribute(&nsm, cudaDevAttrMultiProcessorCount, 0);

    cudaFuncSetAttribute(netvlad_tc_kernel,
                         cudaFuncAttributeMaxDynamicSharedMemorySize, SM_TOTAL);
    const int fin_smem = (Kc * SW_STRIDE + Kc) * (int)sizeof(float);
    cudaFuncSetAttribute(finalize_kernel,
                         cudaFuncAttributeMaxDynamicSharedMemorySize, fin_smem);

    zero_kernel<<<(Kc * Dc + 255) / 256, 256>>>();
    netvlad_tc_kernel<<<nsm, NTHREADS, SM_TOTAL>>>(x, conv_w, conv_b, N, numTiles);
    finalize_kernel<<<1, 256, fin_smem>>>(c, out);
}